// round 2
// baseline (speedup 1.0000x reference)
#include <cuda_runtime.h>
#include <math.h>

// ---------------------------------------------------------------------------
// SoftCluster_adaptiveK: gumbel-softmax k selection + k-means++ init +
// soft k-means (beta=1, tau=1, tol=1e-5, 50 iters with early-freeze).
// Output: centers[k,256] then r[80000,k] concatenated (k derived from out_size).
// ---------------------------------------------------------------------------

#define D      256
#define KMAX   6
#define GRID1  148
#define T1     512
#define NW1    (T1 / 32)
#define TOT_W  (GRID1 * NW1)
#define MAX_ITERS 50
#define TOLV   1e-5

// ---- device scratch (static; no allocation in kernel_launch) ----
__device__ float  g_centers[KMAX * D];
__device__ float  g_prev[KMAX * D];
__device__ float  g_csq[KMAX];
__device__ float  g_w[KMAX];
__device__ float  g_P[GRID1 * KMAX * D];   // per-block partial sums of r^T x
__device__ float  g_Pc[GRID1 * KMAX];      // per-block partial colsums of r
__device__ double g_shiftp[KMAX];
__device__ float  g_dmin[131072];          // N = 80000 fits
__device__ int    g_done;
__device__ int    g_maxiters;
__device__ int    g_idx;

__device__ __forceinline__ float dot4(float4 a, float4 b) {
    return a.x * b.x + a.y * b.y + a.z * b.z + a.w * b.w;
}

// ---------------------------------------------------------------------------
// Init: gumbel-softmax weights, done flag, prev=0, pick center 0, csq[0].
// ---------------------------------------------------------------------------
__global__ void k_init(const float* __restrict__ x,
                       const float* __restrict__ logits,
                       const float* __restrict__ gumbel,
                       const float* __restrict__ uinit,
                       const int*   __restrict__ maxit,
                       int N) {
    __shared__ double s_sq[256];
    int tid = threadIdx.x;
    if (tid == 0) {
        g_maxiters = maxit[0];
        g_done = 0;
        float l[KMAX];
        float m = -3.4e38f;
        for (int j = 0; j < KMAX; j++) {
            l[j] = logits[j] + gumbel[j];           // tau = 1
            m = fmaxf(m, l[j]);
        }
        float s = 0.f;
        float e[KMAX];
        for (int j = 0; j < KMAX; j++) { e[j] = expf(l[j] - m); s += e[j]; }
        for (int j = 0; j < KMAX; j++) g_w[j] = e[j] / s;
        // idx0 = min(int(u0 * N), N-1), fp32 multiply then truncate (matches ref)
        float f = uinit[0] * (float)N;
        int idx = (int)f;
        if (idx > N - 1) idx = N - 1;
        if (idx < 0) idx = 0;
        g_idx = idx;
    }
    for (int i = tid; i < KMAX * D; i += blockDim.x) g_prev[i] = 0.f;
    __syncthreads();
    int idx = g_idx;
    float v = x[(size_t)idx * D + tid];
    g_centers[tid] = v;
    s_sq[tid] = (double)v * (double)v;
    __syncthreads();
    for (int s = 128; s; s >>= 1) {
        if (tid < s) s_sq[tid] += s_sq[tid + s];
        __syncthreads();
    }
    if (tid == 0) g_csq[0] = (float)s_sq[0];
}

// ---------------------------------------------------------------------------
// k-means++ pass: update dmin[n] = min(dmin[n], dist(x_n, centers[i-1])).
// ---------------------------------------------------------------------------
__global__ void __launch_bounds__(T1) k_dmin(const float* __restrict__ x, int N, int i) {
    __shared__ float s_c[D];
    __shared__ float s_cs;
    int tid = threadIdx.x;
    if (tid < D) s_c[tid] = g_centers[(i - 1) * D + tid];
    if (tid == 0) s_cs = g_csq[i - 1];
    __syncthreads();
    int lane = tid & 31;
    int warp = tid >> 5;
    int gwarp = blockIdx.x * (blockDim.x >> 5) + warp;
    int tot = gridDim.x * (blockDim.x >> 5);
    const float4* c4 = (const float4*)s_c;
    float4 c0 = c4[lane], c1 = c4[lane + 32];
    for (int row = gwarp; row < N; row += tot) {
        const float4* xr = (const float4*)(x + (size_t)row * D);
        float4 a0 = __ldg(xr + lane);
        float4 a1 = __ldg(xr + lane + 32);
        float dp = dot4(a0, c0) + dot4(a1, c1);
        float xs = dot4(a0, a0) + dot4(a1, a1);
        #pragma unroll
        for (int m = 16; m; m >>= 1) {
            dp += __shfl_xor_sync(0xffffffffu, dp, m);
            xs += __shfl_xor_sync(0xffffffffu, xs, m);
        }
        if (lane == 0) {
            float d = sqrtf(fmaxf(xs + s_cs - 2.f * dp, 1e-12f));
            g_dmin[row] = (i == 1) ? d : fminf(g_dmin[row], d);
        }
    }
}

// ---------------------------------------------------------------------------
// k-means++ select: double-precision scan of dmin, inverse-CDF draw,
// copy chosen row to centers[i], compute csq[i]. Single block, 1024 threads.
// ---------------------------------------------------------------------------
__global__ void k_select(const float* __restrict__ x,
                         const float* __restrict__ uinit,
                         int N, int i) {
    __shared__ double ss[1024];
    __shared__ double s_sq[256];
    __shared__ int s_idx;
    int tid = threadIdx.x;
    int chunk = (N + 1023) >> 10;
    int st = tid * chunk;
    int en = min(st + chunk, N);
    double s = 0.0;
    for (int n = st; n < en; n++) s += (double)g_dmin[n];
    ss[tid] = s;
    __syncthreads();
    // Hillis-Steele inclusive scan
    for (int off = 1; off < 1024; off <<= 1) {
        double v = (tid >= off) ? ss[tid - off] : 0.0;
        __syncthreads();
        ss[tid] += v;
        __syncthreads();
    }
    double total = ss[1023];
    double target = (double)uinit[i] * total;
    if (tid == 0) s_idx = N - 1;
    __syncthreads();
    double incl = ss[tid];
    double E = incl - s;
    if (target > E && target <= incl) {
        double c = E;
        int f = -1;
        for (int n = st; n < en; n++) {
            c += (double)g_dmin[n];
            if (c >= target) { f = n; break; }
        }
        if (f >= 0) s_idx = f;
    }
    __syncthreads();
    int idx = min(s_idx, N - 1);
    if (tid < D) {
        float v = x[(size_t)idx * D + tid];
        g_centers[i * D + tid] = v;
        s_sq[tid] = (double)v * (double)v;
    }
    __syncthreads();
    for (int sft = 128; sft; sft >>= 1) {
        if (tid < sft) s_sq[tid] += s_sq[tid + sft];
        __syncthreads();
    }
    if (tid == 0) g_csq[i] = (float)s_sq[0];
}

// ---------------------------------------------------------------------------
// K1: fused assign + accumulate. Warp-per-row. Single pass over x.
//   d_j = sqrt(max(xsq + csq_j - 2 x.c_j, 1e-12))
//   r_j = w_j exp(dmin - d_j) / sum_l w_l exp(dmin - d_l)   (stable softmax * w)
// Writes r to output; accumulates r^T x and colsum(r) into per-block partials.
// ---------------------------------------------------------------------------
template <int K>
__global__ void __launch_bounds__(T1) k1_assign(const float* __restrict__ x,
                                                float* __restrict__ out_r,
                                                int N, int t) {
    if (g_done || t >= g_maxiters) return;
    __shared__ float s_c[KMAX * D];
    __shared__ float s_acc[KMAX * D];
    __shared__ float s_csq[KMAX];
    __shared__ float s_w[KMAX];
    __shared__ float s_cnt[KMAX];
    int tid = threadIdx.x;
    for (int i = tid; i < K * D; i += T1) { s_c[i] = g_centers[i]; s_acc[i] = 0.f; }
    if (tid < K) { s_csq[tid] = g_csq[tid]; s_w[tid] = g_w[tid]; s_cnt[tid] = 0.f; }
    __syncthreads();

    int lane = tid & 31;
    int warp = tid >> 5;
    int gwarp = blockIdx.x * NW1 + warp;

    float acc[K][8];
    float cnt[K];
    #pragma unroll
    for (int j = 0; j < K; j++) {
        cnt[j] = 0.f;
        #pragma unroll
        for (int u = 0; u < 8; u++) acc[j][u] = 0.f;
    }

    for (int row = gwarp; row < N; row += TOT_W) {
        const float4* xr = (const float4*)(x + (size_t)row * D);
        float4 a0 = __ldg(xr + lane);
        float4 a1 = __ldg(xr + lane + 32);
        float xs = dot4(a0, a0) + dot4(a1, a1);
        float dp[K];
        #pragma unroll
        for (int j = 0; j < K; j++) {
            const float4* cj = (const float4*)(s_c + j * D);
            dp[j] = dot4(a0, cj[lane]) + dot4(a1, cj[lane + 32]);
        }
        #pragma unroll
        for (int m = 16; m; m >>= 1) {
            xs += __shfl_xor_sync(0xffffffffu, xs, m);
            #pragma unroll
            for (int j = 0; j < K; j++) dp[j] += __shfl_xor_sync(0xffffffffu, dp[j], m);
        }
        float dd[K];
        float dmn = 3.4e38f;
        #pragma unroll
        for (int j = 0; j < K; j++) {
            dd[j] = sqrtf(fmaxf(xs + s_csq[j] - 2.f * dp[j], 1e-12f));
            dmn = fminf(dmn, dd[j]);
        }
        float e[K];
        float ssum = 0.f;
        #pragma unroll
        for (int j = 0; j < K; j++) { e[j] = s_w[j] * expf(dmn - dd[j]); ssum += e[j]; }
        float inv = 1.f / ssum;
        float rv = 0.f;
        #pragma unroll
        for (int j = 0; j < K; j++) {
            float rj = e[j] * inv;
            if (lane == j) rv = rj;
            cnt[j] += rj;
            acc[j][0] = fmaf(rj, a0.x, acc[j][0]);
            acc[j][1] = fmaf(rj, a0.y, acc[j][1]);
            acc[j][2] = fmaf(rj, a0.z, acc[j][2]);
            acc[j][3] = fmaf(rj, a0.w, acc[j][3]);
            acc[j][4] = fmaf(rj, a1.x, acc[j][4]);
            acc[j][5] = fmaf(rj, a1.y, acc[j][5]);
            acc[j][6] = fmaf(rj, a1.z, acc[j][6]);
            acc[j][7] = fmaf(rj, a1.w, acc[j][7]);
        }
        if (lane < K) out_r[(size_t)row * K + lane] = rv;
    }

    // deterministic warp->smem combine (fixed order)
    for (int w = 0; w < NW1; w++) {
        if (warp == w) {
            #pragma unroll
            for (int j = 0; j < K; j++) {
                int b = j * D + 4 * lane;
                s_acc[b + 0]   += acc[j][0];
                s_acc[b + 1]   += acc[j][1];
                s_acc[b + 2]   += acc[j][2];
                s_acc[b + 3]   += acc[j][3];
                s_acc[b + 128] += acc[j][4];
                s_acc[b + 129] += acc[j][5];
                s_acc[b + 130] += acc[j][6];
                s_acc[b + 131] += acc[j][7];
            }
            if (lane == 0) {
                #pragma unroll
                for (int j = 0; j < K; j++) s_cnt[j] += cnt[j];
            }
        }
        __syncthreads();
    }
    float* Pb = g_P + (size_t)blockIdx.x * (KMAX * D);
    for (int i = tid; i < K * D; i += T1) Pb[i] = s_acc[i];
    if (tid < K) g_Pc[blockIdx.x * KMAX + tid] = s_cnt[tid];
}

// ---------------------------------------------------------------------------
// K2: one block per cluster j. Reduce partials (double), new_c = sum/cnt,
// write centers/prev, per-cluster shift^2 partial and csq.
// ---------------------------------------------------------------------------
__global__ void k2_update(int k, int t) {
    int j = blockIdx.x;
    if (j >= k) return;
    if (g_done || t >= g_maxiters) return;
    __shared__ double s_red[256];
    __shared__ double s_cnt;
    int tid = threadIdx.x;
    if (tid < 32) {
        double c = 0.0;
        for (int p = tid; p < GRID1; p += 32) c += (double)g_Pc[p * KMAX + j];
        #pragma unroll
        for (int m = 16; m; m >>= 1) c += __shfl_down_sync(0xffffffffu, c, m);
        if (tid == 0) s_cnt = c;
    }
    __syncthreads();
    double cs = s_cnt;
    int e = j * D + tid;
    double sum = 0.0;
    #pragma unroll 4
    for (int p = 0; p < GRID1; p++) sum += (double)g_P[(size_t)p * (KMAX * D) + e];
    float ncf = (float)(sum / cs);
    g_centers[e] = ncf;
    float pv = g_prev[e];
    g_prev[e] = ncf;
    double df = (double)(ncf - pv);
    s_red[tid] = df * df;
    __syncthreads();
    for (int s = 128; s; s >>= 1) {
        if (tid < s) s_red[tid] += s_red[tid + s];
        __syncthreads();
    }
    if (tid == 0) g_shiftp[j] = s_red[0];
    __syncthreads();
    s_red[tid] = (double)ncf * (double)ncf;
    __syncthreads();
    for (int s = 128; s; s >>= 1) {
        if (tid < s) s_red[tid] += s_red[tid + s];
        __syncthreads();
    }
    if (tid == 0) g_csq[j] = (float)s_red[0];
}

// ---------------------------------------------------------------------------
// K3: convergence check. Sets done AFTER centers/r were updated this iter
// (matches the reference scan's use of the pre-update done flag).
// ---------------------------------------------------------------------------
__global__ void k3_check(int k, int t) {
    if (g_done || t >= g_maxiters) return;
    if (threadIdx.x == 0) {
        double s = 0.0;
        for (int j = 0; j < k; j++) s += g_shiftp[j];
        if (sqrt(s) < TOLV) g_done = 1;
    }
}

__global__ void k_copy(float* __restrict__ out_c, int k) {
    for (int i = threadIdx.x; i < k * D; i += blockDim.x) out_c[i] = g_centers[i];
}

// ---------------------------------------------------------------------------
extern "C" void kernel_launch(void* const* d_in, const int* in_sizes, int n_in,
                              void* d_out, int out_size) {
    const float* x      = (const float*)d_in[0];
    const float* logits = (const float*)d_in[1];
    const float* gumbel = (const float*)d_in[2];
    const float* uinit  = (const float*)d_in[3];
    const int*   maxit  = (const int*)d_in[4];

    int N = in_sizes[0] / D;
    int k = out_size / (N + D);     // out = centers[k*D] + r[N*k]
    if (k < 1) k = 1;
    if (k > KMAX) k = KMAX;

    float* out_c = (float*)d_out;
    float* out_r = out_c + (size_t)k * D;

    k_init<<<1, 256>>>(x, logits, gumbel, uinit, maxit, N);
    for (int i = 1; i < k; i++) {
        k_dmin<<<GRID1, T1>>>(x, N, i);
        k_select<<<1, 1024>>>(x, uinit, N, i);
    }
    for (int t = 0; t < MAX_ITERS; t++) {
        switch (k) {
            case 1: k1_assign<1><<<GRID1, T1>>>(x, out_r, N, t); break;
            case 2: k1_assign<2><<<GRID1, T1>>>(x, out_r, N, t); break;
            case 3: k1_assign<3><<<GRID1, T1>>>(x, out_r, N, t); break;
            case 4: k1_assign<4><<<GRID1, T1>>>(x, out_r, N, t); break;
            case 5: k1_assign<5><<<GRID1, T1>>>(x, out_r, N, t); break;
            default: k1_assign<6><<<GRID1, T1>>>(x, out_r, N, t); break;
        }
        k2_update<<<KMAX, 256>>>(k, t);
        k3_check<<<1, 32>>>(k, t);
    }
    k_copy<<<1, 256>>>(out_c, k);
}

// round 4
// speedup vs baseline: 1.4433x; 1.4433x over previous
#include <cuda_runtime.h>
#include <math.h>

// ---------------------------------------------------------------------------
// SoftCluster_adaptiveK — round 4
//  * ONE persistent kernel runs all 50 soft-kmeans iterations with a software
//    grid barrier; early-converged iterations cost ~0 (in-kernel break).
//  * packed fma.rn.f32x2 for dots + accumulation (halves FFMA stream)
//  * lane-parallel epilogue (lane j owns cluster j) -> 3 MUFU/row
//  * xsq precomputed once; butterfly shuffles (redux.f32 unsupported on sm_103)
//  * cross-block traffic inside the persistent kernel uses __ldcg (L1 is not
//    coherent across SMs within a single launch)
// ---------------------------------------------------------------------------

#define D      256
#define KMAX   6
#define GRID1  148
#define T1     384
#define NW1    (T1 / 32)
#define TOT_W  (GRID1 * NW1)
#define GRIDM  592
#define TM     256
#define TOT_WM (GRIDM * (TM / 32))
#define TOLV   1e-5

typedef unsigned long long u64;

// ---- device scratch (static; no allocation anywhere) ----
__device__ float  g_centers[KMAX * D];
__device__ float  g_prev[KMAX * D];
__device__ float  g_csq[KMAX];
__device__ float  g_w[KMAX];
__device__ float  g_P[GRID1 * KMAX * D];
__device__ float  g_Pc[GRID1 * KMAX];
__device__ double g_shiftp[KMAX];
__device__ float  g_dmin[131072];
__device__ float  g_xsq[131072];
__device__ int    g_maxiters;
__device__ int    g_idx;
__device__ int    g_bar_count;
__device__ int    g_bar_phase;

// ---- helpers ----
__device__ __forceinline__ u64 pk2(float lo, float hi) {
    u64 r; asm("mov.b64 %0,{%1,%2};" : "=l"(r) : "f"(lo), "f"(hi)); return r;
}
__device__ __forceinline__ void upk2(u64 v, float& lo, float& hi) {
    asm("mov.b64 {%0,%1},%2;" : "=f"(lo), "=f"(hi) : "l"(v));
}
__device__ __forceinline__ u64 fma2(u64 a, u64 b, u64 c) {
    u64 r; asm("fma.rn.f32x2 %0,%1,%2,%3;" : "=l"(r) : "l"(a), "l"(b), "l"(c)); return r;
}
__device__ __forceinline__ u64 mul2(u64 a, u64 b) {
    u64 r; asm("mul.rn.f32x2 %0,%1,%2;" : "=l"(r) : "l"(a), "l"(b)); return r;
}
__device__ __forceinline__ float wsum(float v) {
    #pragma unroll
    for (int m = 16; m; m >>= 1) v += __shfl_xor_sync(0xffffffffu, v, m);
    return v;
}
__device__ __forceinline__ float wsum8(float v) {   // sum within 8-lane groups
    v += __shfl_xor_sync(0xffffffffu, v, 1);
    v += __shfl_xor_sync(0xffffffffu, v, 2);
    v += __shfl_xor_sync(0xffffffffu, v, 4);
    return v;
}
__device__ __forceinline__ float wmin8(float v) {   // min within 8-lane groups
    v = fminf(v, __shfl_xor_sync(0xffffffffu, v, 1));
    v = fminf(v, __shfl_xor_sync(0xffffffffu, v, 2));
    v = fminf(v, __shfl_xor_sync(0xffffffffu, v, 4));
    return v;
}
__device__ __forceinline__ float dot4(float4 a, float4 b) {
    return a.x * b.x + a.y * b.y + a.z * b.z + a.w * b.w;
}

// software grid barrier (all GRID1 blocks resident by construction)
__device__ __forceinline__ void grid_sync() {
    __syncthreads();
    if (threadIdx.x == 0) {
        __threadfence();
        int ph = atomicAdd(&g_bar_phase, 0);
        if (atomicAdd(&g_bar_count, 1) == (int)gridDim.x - 1) {
            atomicExch(&g_bar_count, 0);
            __threadfence();
            atomicExch(&g_bar_phase, ph + 1);
        } else {
            while (atomicAdd(&g_bar_phase, 0) == ph) { __nanosleep(64); }
            __threadfence();
        }
    }
    __syncthreads();
}

// ---------------------------------------------------------------------------
// Init: gumbel-softmax weights, flags, prev=0, pick center 0, csq[0].
// ---------------------------------------------------------------------------
__global__ void k_init(const float* __restrict__ x,
                       const float* __restrict__ logits,
                       const float* __restrict__ gumbel,
                       const float* __restrict__ uinit,
                       const int*   __restrict__ maxit,
                       int N) {
    __shared__ double s_sq[256];
    int tid = threadIdx.x;
    if (tid == 0) {
        g_maxiters = maxit[0];
        g_bar_count = 0;
        g_bar_phase = 0;
        float l[KMAX];
        float m = -3.4e38f;
        for (int j = 0; j < KMAX; j++) {
            l[j] = logits[j] + gumbel[j];           // tau = 1
            m = fmaxf(m, l[j]);
        }
        float s = 0.f;
        float e[KMAX];
        for (int j = 0; j < KMAX; j++) { e[j] = expf(l[j] - m); s += e[j]; }
        for (int j = 0; j < KMAX; j++) g_w[j] = e[j] / s;
        float f = uinit[0] * (float)N;
        int idx = (int)f;
        if (idx > N - 1) idx = N - 1;
        if (idx < 0) idx = 0;
        g_idx = idx;
    }
    for (int i = tid; i < KMAX * D; i += blockDim.x) g_prev[i] = 0.f;
    __syncthreads();
    int idx = g_idx;
    float v = x[(size_t)idx * D + tid];
    g_centers[tid] = v;
    s_sq[tid] = (double)v * (double)v;
    __syncthreads();
    for (int s = 128; s; s >>= 1) {
        if (tid < s) s_sq[tid] += s_sq[tid + s];
        __syncthreads();
    }
    if (tid == 0) g_csq[0] = (float)s_sq[0];
}

// ---------------------------------------------------------------------------
// xsq[n] = ||x_n||^2 (iteration-invariant).
// ---------------------------------------------------------------------------
__global__ void __launch_bounds__(TM) k_xsq(const float* __restrict__ x, int N) {
    int tid = threadIdx.x;
    int lane = tid & 31;
    int gwarp = blockIdx.x * (TM / 32) + (tid >> 5);
    for (int row = gwarp; row < N; row += TOT_WM) {
        const float4* xr = (const float4*)x + (size_t)row * (D / 4);
        float4 a0 = __ldg(xr + lane);
        float4 a1 = __ldg(xr + lane + 32);
        float xs = wsum(dot4(a0, a0) + dot4(a1, a1));
        if (lane == 0) g_xsq[row] = xs;
    }
}

// ---------------------------------------------------------------------------
// k-means++ pass: dmin[n] = min(dmin[n], dist(x_n, centers[i-1])).
// ---------------------------------------------------------------------------
__global__ void __launch_bounds__(TM) k_dmin(const float* __restrict__ x, int N, int i) {
    __shared__ float s_c[D];
    __shared__ float s_cs;
    int tid = threadIdx.x;
    if (tid < D) s_c[tid] = g_centers[(i - 1) * D + tid];
    if (tid == 0) s_cs = g_csq[i - 1];
    __syncthreads();
    int lane = tid & 31;
    int gwarp = blockIdx.x * (TM / 32) + (tid >> 5);
    const float4* c4 = (const float4*)s_c;
    float4 c0 = c4[lane], c1 = c4[lane + 32];
    for (int row = gwarp; row < N; row += TOT_WM) {
        const float4* xr = (const float4*)x + (size_t)row * (D / 4);
        float4 a0 = __ldg(xr + lane);
        float4 a1 = __ldg(xr + lane + 32);
        float dp = wsum(dot4(a0, c0) + dot4(a1, c1));
        if (lane == 0) {
            float xs = g_xsq[row];
            float d = sqrtf(fmaxf(xs + s_cs - 2.f * dp, 1e-12f));
            g_dmin[row] = (i == 1) ? d : fminf(g_dmin[row], d);
        }
    }
}

// ---------------------------------------------------------------------------
// k-means++ select: double-precision scan of dmin + inverse-CDF draw.
// ---------------------------------------------------------------------------
__global__ void k_select(const float* __restrict__ x,
                         const float* __restrict__ uinit,
                         int N, int i) {
    __shared__ double ss[1024];
    __shared__ double s_sq[256];
    __shared__ int s_idx;
    int tid = threadIdx.x;
    int chunk = (N + 1023) >> 10;
    int st = tid * chunk;
    int en = min(st + chunk, N);
    double s0 = 0.0, s1 = 0.0, s2 = 0.0, s3 = 0.0;
    int n = st;
    for (; n + 3 < en; n += 4) {
        s0 += (double)g_dmin[n];
        s1 += (double)g_dmin[n + 1];
        s2 += (double)g_dmin[n + 2];
        s3 += (double)g_dmin[n + 3];
    }
    for (; n < en; n++) s0 += (double)g_dmin[n];
    double s = (s0 + s1) + (s2 + s3);
    ss[tid] = s;
    __syncthreads();
    for (int off = 1; off < 1024; off <<= 1) {
        double v = (tid >= off) ? ss[tid - off] : 0.0;
        __syncthreads();
        ss[tid] += v;
        __syncthreads();
    }
    double total = ss[1023];
    double target = (double)uinit[i] * total;
    if (tid == 0) s_idx = N - 1;
    __syncthreads();
    double incl = ss[tid];
    double E = incl - s;
    if (target > E && target <= incl) {
        double c = E;
        int f = -1;
        for (int m = st; m < en; m++) {
            c += (double)g_dmin[m];
            if (c >= target) { f = m; break; }
        }
        if (f < 0) f = en - 1;
        s_idx = f;
    }
    __syncthreads();
    int idx = min(s_idx, N - 1);
    if (tid < D) {
        float v = x[(size_t)idx * D + tid];
        g_centers[i * D + tid] = v;
        s_sq[tid] = (double)v * (double)v;
    }
    __syncthreads();
    for (int sft = 128; sft; sft >>= 1) {
        if (tid < sft) s_sq[tid] += s_sq[tid + sft];
        __syncthreads();
    }
    if (tid == 0) g_csq[i] = (float)s_sq[0];
}

// ---------------------------------------------------------------------------
// Persistent iteration kernel: all soft-kmeans iterations in one launch.
// Per iteration: fused assign+accumulate (warp-per-row), grid barrier,
// center update (blocks 0..K-1), grid barrier, uniform convergence check.
// ---------------------------------------------------------------------------
template <int K>
__global__ void __launch_bounds__(T1) k_iter(const float* __restrict__ x,
                                             float* __restrict__ out_r,
                                             float* __restrict__ out_c,
                                             int N) {
    __shared__ float4 s_acc4[K * 64];
    __shared__ float  s_cnt[K];
    __shared__ double s_red[T1];

    int tid  = threadIdx.x;
    int lane = tid & 31;
    int warp = tid >> 5;
    int bid  = blockIdx.x;
    int maxit = g_maxiters;

    if (maxit < 1) {    // reference scan length 0: r = zeros, centers = init
        size_t tot = (size_t)N * K;
        for (size_t i = (size_t)bid * T1 + tid; i < tot; i += (size_t)GRID1 * T1)
            out_r[i] = 0.f;
        if (bid == 0)
            for (int i = tid; i < K * D; i += T1) out_c[i] = g_centers[i];
        return;
    }

    float w_l = (lane < K) ? __ldg(&g_w[lane]) : 0.f;

    for (int t = 0; t < maxit; t++) {
        // ---- load current centers (cross-block mutable -> .cg) ----
        float csq_l = (lane < K) ? __ldcg(&g_csq[lane]) : 0.f;
        u64 c_pk[K][4];
        const float4* cb = (const float4*)g_centers;
        #pragma unroll
        for (int j = 0; j < K; j++) {
            float4 c0 = __ldcg(cb + j * 64 + lane);
            float4 c1 = __ldcg(cb + j * 64 + 32 + lane);
            c_pk[j][0] = pk2(c0.x, c0.y); c_pk[j][1] = pk2(c0.z, c0.w);
            c_pk[j][2] = pk2(c1.x, c1.y); c_pk[j][3] = pk2(c1.z, c1.w);
        }
        for (int i = tid; i < K * 64; i += T1) s_acc4[i] = make_float4(0.f, 0.f, 0.f, 0.f);
        if (tid < K) s_cnt[tid] = 0.f;
        __syncthreads();

        u64 acc2[K][4];
        #pragma unroll
        for (int j = 0; j < K; j++) {
            #pragma unroll
            for (int u = 0; u < 4; u++) acc2[j][u] = 0ull;
        }
        float cnt_l = 0.f;

        // ---- main pass over rows ----
        int row = bid * NW1 + warp;
        float4 a0, a1; float xs = 0.f;
        if (row < N) {
            const float4* xr = (const float4*)x + (size_t)row * (D / 4);
            a0 = __ldg(xr + lane);
            a1 = __ldg(xr + lane + 32);
            xs = __ldg(g_xsq + row);
        }
        while (row < N) {
            int nrow = row + TOT_W;
            float4 b0, b1; float nxs = 0.f;
            if (nrow < N) {
                const float4* xn = (const float4*)x + (size_t)nrow * (D / 4);
                b0 = __ldg(xn + lane);
                b1 = __ldg(xn + lane + 32);
                nxs = __ldg(g_xsq + nrow);
            }
            u64 p0 = pk2(a0.x, a0.y), p1 = pk2(a0.z, a0.w);
            u64 p2 = pk2(a1.x, a1.y), p3 = pk2(a1.z, a1.w);
            float dp[K];
            #pragma unroll
            for (int j = 0; j < K; j++) {
                u64 tt = mul2(p0, c_pk[j][0]);
                tt = fma2(p1, c_pk[j][1], tt);
                tt = fma2(p2, c_pk[j][2], tt);
                tt = fma2(p3, c_pk[j][3], tt);
                float lo, hi; upk2(tt, lo, hi);
                dp[j] = lo + hi;
            }
            #pragma unroll
            for (int j = 0; j < K; j++) dp[j] = wsum(dp[j]);
            float mydp = dp[0];
            #pragma unroll
            for (int j = 1; j < K; j++) mydp = (lane == j) ? dp[j] : mydp;
            float dval = sqrtf(fmaxf(xs + csq_l - 2.f * mydp, 1e-12f));
            float dmn  = wmin8((lane < K) ? dval : 3.4e38f);
            float ev   = w_l * __expf(dmn - dval);
            float ssum = wsum8(ev);
            float rv   = __fdividef(ev, ssum);
            if (lane < K) out_r[(size_t)row * K + lane] = rv;
            cnt_l += rv;
            float rb[K];
            #pragma unroll
            for (int j = 0; j < K; j++) rb[j] = __shfl_sync(0xffffffffu, rv, j);
            #pragma unroll
            for (int j = 0; j < K; j++) {
                u64 r2 = pk2(rb[j], rb[j]);
                acc2[j][0] = fma2(r2, p0, acc2[j][0]);
                acc2[j][1] = fma2(r2, p1, acc2[j][1]);
                acc2[j][2] = fma2(r2, p2, acc2[j][2]);
                acc2[j][3] = fma2(r2, p3, acc2[j][3]);
            }
            a0 = b0; a1 = b1; xs = nxs;
            row = nrow;
        }

        // ---- deterministic sequential warp combine ----
        for (int w = 0; w < NW1; w++) {
            if (warp == w) {
                #pragma unroll
                for (int j = 0; j < K; j++) {
                    float lo0, hi0, lo1, hi1;
                    float4 v = s_acc4[j * 64 + lane];
                    upk2(acc2[j][0], lo0, hi0);
                    upk2(acc2[j][1], lo1, hi1);
                    v.x += lo0; v.y += hi0; v.z += lo1; v.w += hi1;
                    s_acc4[j * 64 + lane] = v;
                    v = s_acc4[j * 64 + 32 + lane];
                    upk2(acc2[j][2], lo0, hi0);
                    upk2(acc2[j][3], lo1, hi1);
                    v.x += lo0; v.y += hi0; v.z += lo1; v.w += hi1;
                    s_acc4[j * 64 + 32 + lane] = v;
                }
                if (lane < K) s_cnt[lane] += cnt_l;
            }
            __syncthreads();
        }
        {
            float4* Pb = (float4*)(g_P + (size_t)bid * (KMAX * D));
            for (int i = tid; i < K * 64; i += T1) Pb[i] = s_acc4[i];
            if (tid < K) g_Pc[bid * KMAX + tid] = s_cnt[tid];
        }

        grid_sync();

        // ---- center update: block j < K owns cluster j ----
        if (bid < K) {
            int j = bid;
            double c = 0.0;
            for (int p = tid; p < GRID1; p += T1)
                c += (double)__ldcg(&g_Pc[p * KMAX + j]);
            s_red[tid] = c;
            __syncthreads();
            for (int s = 256; s; s >>= 1) {
                if (tid < s && tid + s < T1) s_red[tid] += s_red[tid + s];
                __syncthreads();
            }
            double cnt = s_red[0];
            __syncthreads();

            double v0 = 0.0, v1 = 0.0;   // per-element sums (tid < 256)
            if (tid < 256) {
                int e = j * D + tid;
                double su0 = 0.0, su1 = 0.0, su2 = 0.0, su3 = 0.0;
                int p = 0;
                for (; p + 3 < GRID1; p += 4) {
                    su0 += (double)__ldcg(&g_P[(size_t)(p)     * (KMAX * D) + e]);
                    su1 += (double)__ldcg(&g_P[(size_t)(p + 1) * (KMAX * D) + e]);
                    su2 += (double)__ldcg(&g_P[(size_t)(p + 2) * (KMAX * D) + e]);
                    su3 += (double)__ldcg(&g_P[(size_t)(p + 3) * (KMAX * D) + e]);
                }
                for (; p < GRID1; p++)
                    su0 += (double)__ldcg(&g_P[(size_t)p * (KMAX * D) + e]);
                double sum = (su0 + su1) + (su2 + su3);
                float ncf = (float)(sum / cnt);
                g_centers[e] = ncf;
                float pv = g_prev[e];
                g_prev[e] = ncf;
                double df = (double)(ncf - pv);
                v0 = df * df;
                v1 = (double)ncf * (double)ncf;
            }
            s_red[tid] = v0;
            __syncthreads();
            for (int s = 256; s; s >>= 1) {
                if (tid < s && tid + s < T1) s_red[tid] += s_red[tid + s];
                __syncthreads();
            }
            if (tid == 0) g_shiftp[j] = s_red[0];
            __syncthreads();
            s_red[tid] = v1;
            __syncthreads();
            for (int s = 256; s; s >>= 1) {
                if (tid < s && tid + s < T1) s_red[tid] += s_red[tid + s];
                __syncthreads();
            }
            if (tid == 0) g_csq[j] = (float)s_red[0];
        }

        grid_sync();

        // ---- uniform convergence check (every block computes identically) ----
        double sh = 0.0;
        #pragma unroll
        for (int j = 0; j < K; j++) sh += __ldcg(&g_shiftp[j]);
        if (sqrt(sh) < TOLV) break;
    }

    if (bid == 0)
        for (int i = tid; i < K * D; i += T1) out_c[i] = __ldcg(&g_centers[i]);
}

// ---------------------------------------------------------------------------
extern "C" void kernel_launch(void* const* d_in, const int* in_sizes, int n_in,
                              void* d_out, int out_size) {
    const float* x      = (const float*)d_in[0];
    const float* logits = (const float*)d_in[1];
    const float* gumbel = (const float*)d_in[2];
    const float* uinit  = (const float*)d_in[3];
    const int*   maxit  = (const int*)d_in[4];

    int N = in_sizes[0] / D;
    int k = out_size / (N + D);     // out = centers[k*D] + r[N*k]
    if (k < 1) k = 1;
    if (k > KMAX) k = KMAX;

    float* out_c = (float*)d_out;
    float* out_r = out_c + (size_t)k * D;

    k_init<<<1, 256>>>(x, logits, gumbel, uinit, maxit, N);
    k_xsq<<<GRIDM, TM>>>(x, N);
    for (int i = 1; i < k; i++) {
        k_dmin<<<GRIDM, TM>>>(x, N, i);
        k_select<<<1, 1024>>>(x, uinit, N, i);
    }
    switch (k) {
        case 1: k_iter<1><<<GRID1, T1>>>(x, out_r, out_c, N); break;
        case 2: k_iter<2><<<GRID1, T1>>>(x, out_r, out_c, N); break;
        case 3: k_iter<3><<<GRID1, T1>>>(x, out_r, out_c, N); break;
        case 4: k_iter<4><<<GRID1, T1>>>(x, out_r, out_c, N); break;
        case 5: k_iter<5><<<GRID1, T1>>>(x, out_r, out_c, N); break;
        default: k_iter<6><<<GRID1, T1>>>(x, out_r, out_c, N); break;
    }
}

// round 5
// speedup vs baseline: 1.8632x; 1.2909x over previous
#include <cuda_runtime.h>
#include <math.h>

// ---------------------------------------------------------------------------
// SoftCluster_adaptiveK — round 5
//  * two-level k-means++ select: contiguous-chunk k_dmin emits per-block sums;
//    select scans 592 block sums then <=136 rows (61us -> ~4us per call)
//  * persistent iteration kernel (unchanged structure) with:
//      - 2-row interleaved mainloop (hides shuffle-chain latency)
//      - MLP-8 update-phase reduction
// ---------------------------------------------------------------------------

#define D      256
#define KMAX   6
#define GRID1  148
#define T1     384
#define NW1    (T1 / 32)
#define TOT_W  (GRID1 * NW1)
#define DB     592
#define TM     256
#define TOLV   1e-5

typedef unsigned long long u64;

// ---- device scratch (static; no allocation anywhere) ----
__device__ float  g_centers[KMAX * D];
__device__ float  g_prev[KMAX * D];
__device__ float  g_csq[KMAX];
__device__ float  g_w[KMAX];
__device__ float  g_P[GRID1 * KMAX * D];
__device__ float  g_Pc[GRID1 * KMAX];
__device__ double g_shiftp[KMAX];
__device__ float  g_dmin[131072];
__device__ float  g_xsq[131072];
__device__ double g_bsum[DB];
__device__ int    g_maxiters;
__device__ int    g_idx;
__device__ int    g_bar_count;
__device__ int    g_bar_phase;

// ---- helpers ----
__device__ __forceinline__ u64 pk2(float lo, float hi) {
    u64 r; asm("mov.b64 %0,{%1,%2};" : "=l"(r) : "f"(lo), "f"(hi)); return r;
}
__device__ __forceinline__ void upk2(u64 v, float& lo, float& hi) {
    asm("mov.b64 {%0,%1},%2;" : "=f"(lo), "=f"(hi) : "l"(v));
}
__device__ __forceinline__ u64 fma2(u64 a, u64 b, u64 c) {
    u64 r; asm("fma.rn.f32x2 %0,%1,%2,%3;" : "=l"(r) : "l"(a), "l"(b), "l"(c)); return r;
}
__device__ __forceinline__ u64 mul2(u64 a, u64 b) {
    u64 r; asm("mul.rn.f32x2 %0,%1,%2;" : "=l"(r) : "l"(a), "l"(b)); return r;
}
__device__ __forceinline__ float wsum(float v) {
    #pragma unroll
    for (int m = 16; m; m >>= 1) v += __shfl_xor_sync(0xffffffffu, v, m);
    return v;
}
__device__ __forceinline__ float wsum8(float v) {
    v += __shfl_xor_sync(0xffffffffu, v, 1);
    v += __shfl_xor_sync(0xffffffffu, v, 2);
    v += __shfl_xor_sync(0xffffffffu, v, 4);
    return v;
}
__device__ __forceinline__ float wmin8(float v) {
    v = fminf(v, __shfl_xor_sync(0xffffffffu, v, 1));
    v = fminf(v, __shfl_xor_sync(0xffffffffu, v, 2));
    v = fminf(v, __shfl_xor_sync(0xffffffffu, v, 4));
    return v;
}
__device__ __forceinline__ float dot4(float4 a, float4 b) {
    return a.x * b.x + a.y * b.y + a.z * b.z + a.w * b.w;
}

// software grid barrier (all GRID1 blocks resident by construction)
__device__ __forceinline__ void grid_sync() {
    __syncthreads();
    if (threadIdx.x == 0) {
        __threadfence();
        int ph = atomicAdd(&g_bar_phase, 0);
        if (atomicAdd(&g_bar_count, 1) == (int)gridDim.x - 1) {
            atomicExch(&g_bar_count, 0);
            __threadfence();
            atomicExch(&g_bar_phase, ph + 1);
        } else {
            while (atomicAdd(&g_bar_phase, 0) == ph) { __nanosleep(64); }
            __threadfence();
        }
    }
    __syncthreads();
}

// ---------------------------------------------------------------------------
__global__ void k_init(const float* __restrict__ x,
                       const float* __restrict__ logits,
                       const float* __restrict__ gumbel,
                       const float* __restrict__ uinit,
                       const int*   __restrict__ maxit,
                       int N) {
    __shared__ double s_sq[256];
    int tid = threadIdx.x;
    if (tid == 0) {
        g_maxiters = maxit[0];
        g_bar_count = 0;
        g_bar_phase = 0;
        float l[KMAX];
        float m = -3.4e38f;
        for (int j = 0; j < KMAX; j++) {
            l[j] = logits[j] + gumbel[j];
            m = fmaxf(m, l[j]);
        }
        float s = 0.f;
        float e[KMAX];
        for (int j = 0; j < KMAX; j++) { e[j] = expf(l[j] - m); s += e[j]; }
        for (int j = 0; j < KMAX; j++) g_w[j] = e[j] / s;
        float f = uinit[0] * (float)N;
        int idx = (int)f;
        if (idx > N - 1) idx = N - 1;
        if (idx < 0) idx = 0;
        g_idx = idx;
    }
    for (int i = tid; i < KMAX * D; i += blockDim.x) g_prev[i] = 0.f;
    __syncthreads();
    int idx = g_idx;
    float v = x[(size_t)idx * D + tid];
    g_centers[tid] = v;
    s_sq[tid] = (double)v * (double)v;
    __syncthreads();
    for (int s = 128; s; s >>= 1) {
        if (tid < s) s_sq[tid] += s_sq[tid + s];
        __syncthreads();
    }
    if (tid == 0) g_csq[0] = (float)s_sq[0];
}

// ---------------------------------------------------------------------------
// xsq[n] = ||x_n||^2
// ---------------------------------------------------------------------------
__global__ void __launch_bounds__(TM) k_xsq(const float* __restrict__ x, int N) {
    int tid = threadIdx.x;
    int lane = tid & 31;
    int gwarp = blockIdx.x * (TM / 32) + (tid >> 5);
    int tot = DB * (TM / 32);
    for (int row = gwarp; row < N; row += tot) {
        const float4* xr = (const float4*)x + (size_t)row * (D / 4);
        float4 a0 = __ldg(xr + lane);
        float4 a1 = __ldg(xr + lane + 32);
        float xs = wsum(dot4(a0, a0) + dot4(a1, a1));
        if (lane == 0) g_xsq[row] = xs;
    }
}

// ---------------------------------------------------------------------------
// k-means++ pass over CONTIGUOUS chunk: dmin update + per-block double sum.
// ---------------------------------------------------------------------------
__global__ void __launch_bounds__(TM) k_dmin(const float* __restrict__ x, int N, int i) {
    __shared__ float  s_c[D];
    __shared__ float  s_cs;
    __shared__ double s_ws[TM / 32];
    int tid = threadIdx.x;
    if (tid < D) s_c[tid] = g_centers[(i - 1) * D + tid];
    if (tid == 0) s_cs = g_csq[i - 1];
    if (tid < TM / 32) s_ws[tid] = 0.0;
    __syncthreads();
    int lane = tid & 31;
    int warp = tid >> 5;
    int chunk = (N + DB - 1) / DB;
    int st = blockIdx.x * chunk;
    int en = min(st + chunk, N);
    const float4* c4 = (const float4*)s_c;
    float4 c0 = c4[lane], c1 = c4[lane + 32];
    double wsumd = 0.0;
    for (int row = st + warp; row < en; row += TM / 32) {
        const float4* xr = (const float4*)x + (size_t)row * (D / 4);
        float4 a0 = __ldg(xr + lane);
        float4 a1 = __ldg(xr + lane + 32);
        float dp = wsum(dot4(a0, c0) + dot4(a1, c1));
        if (lane == 0) {
            float xs = g_xsq[row];
            float d = sqrtf(fmaxf(xs + s_cs - 2.f * dp, 1e-12f));
            float nd = (i == 1) ? d : fminf(g_dmin[row], d);
            g_dmin[row] = nd;
            wsumd += (double)nd;
        }
    }
    if (lane == 0) s_ws[warp] = wsumd;
    __syncthreads();
    if (tid == 0) {
        double s = 0.0;
        #pragma unroll
        for (int w = 0; w < TM / 32; w++) s += s_ws[w];
        g_bsum[blockIdx.x] = s;
    }
}

// ---------------------------------------------------------------------------
// k-means++ select: two-level scan (block sums, then rows of target block).
// ---------------------------------------------------------------------------
__global__ void k_select(const float* __restrict__ x,
                         const float* __restrict__ uinit,
                         int N, int i) {
    __shared__ double ss[1024];
    __shared__ double s_sq[256];
    __shared__ double s_base;
    __shared__ int    s_pick;
    int tid = threadIdx.x;
    int chunk = (N + DB - 1) / DB;

    // level 1: scan block sums
    double v = (tid < DB) ? g_bsum[tid] : 0.0;
    ss[tid] = v;
    __syncthreads();
    for (int off = 1; off < 1024; off <<= 1) {
        double u = (tid >= off) ? ss[tid - off] : 0.0;
        __syncthreads();
        ss[tid] += u;
        __syncthreads();
    }
    double total  = ss[1023];
    double target = (double)uinit[i] * total;
    if (tid == 0) { s_pick = DB - 1; s_base = total - v; }  // fallback
    __syncthreads();
    if (tid < DB) {
        double incl = ss[tid];
        double excl = incl - v;
        if (excl < target && target <= incl) { s_pick = tid; s_base = excl; }
    }
    __syncthreads();
    int tb = s_pick;
    double base = s_base;
    int st  = tb * chunk;
    int en  = min(st + chunk, N);
    int cnt = en - st;
    double resid = target - base;
    double rv = (tid < cnt) ? (double)g_dmin[st + tid] : 0.0;
    __syncthreads();

    // level 2: scan rows of the target block
    ss[tid] = rv;
    if (tid == 0) s_pick = cnt - 1;   // fallback
    __syncthreads();
    for (int off = 1; off < 1024; off <<= 1) {
        double u = (tid >= off) ? ss[tid - off] : 0.0;
        __syncthreads();
        ss[tid] += u;
        __syncthreads();
    }
    if (tid < cnt) {
        double incl = ss[tid];
        double excl = incl - rv;
        if (excl < resid && resid <= incl) s_pick = tid;
    }
    __syncthreads();
    int idx = st + s_pick;
    if (idx > N - 1) idx = N - 1;

    // copy chosen row -> centers[i], compute csq[i]
    if (tid < D) {
        float cv = x[(size_t)idx * D + tid];
        g_centers[i * D + tid] = cv;
        s_sq[tid] = (double)cv * (double)cv;
    }
    __syncthreads();
    for (int sft = 128; sft; sft >>= 1) {
        if (tid < sft) s_sq[tid] += s_sq[tid + sft];
        __syncthreads();
    }
    if (tid == 0) g_csq[i] = (float)s_sq[0];
}

// ---------------------------------------------------------------------------
// Persistent iteration kernel.
// ---------------------------------------------------------------------------
template <int K>
__global__ void __launch_bounds__(T1) k_iter(const float* __restrict__ x,
                                             float* __restrict__ out_r,
                                             float* __restrict__ out_c,
                                             int N) {
    __shared__ float4 s_acc4[K * 64];
    __shared__ float  s_cnt[K];
    __shared__ double s_red[T1];

    int tid  = threadIdx.x;
    int lane = tid & 31;
    int warp = tid >> 5;
    int bid  = blockIdx.x;
    int maxit = g_maxiters;

    if (maxit < 1) {
        size_t tot = (size_t)N * K;
        for (size_t i = (size_t)bid * T1 + tid; i < tot; i += (size_t)GRID1 * T1)
            out_r[i] = 0.f;
        if (bid == 0)
            for (int i = tid; i < K * D; i += T1) out_c[i] = g_centers[i];
        return;
    }

    float w_l = (lane < K) ? __ldg(&g_w[lane]) : 0.f;

    for (int t = 0; t < maxit; t++) {
        float csq_l = (lane < K) ? __ldcg(&g_csq[lane]) : 0.f;
        u64 c_pk[K][4];
        const float4* cb = (const float4*)g_centers;
        #pragma unroll
        for (int j = 0; j < K; j++) {
            float4 c0 = __ldcg(cb + j * 64 + lane);
            float4 c1 = __ldcg(cb + j * 64 + 32 + lane);
            c_pk[j][0] = pk2(c0.x, c0.y); c_pk[j][1] = pk2(c0.z, c0.w);
            c_pk[j][2] = pk2(c1.x, c1.y); c_pk[j][3] = pk2(c1.z, c1.w);
        }
        for (int i = tid; i < K * 64; i += T1) s_acc4[i] = make_float4(0.f, 0.f, 0.f, 0.f);
        if (tid < K) s_cnt[tid] = 0.f;
        __syncthreads();

        u64 acc2[K][4];
        #pragma unroll
        for (int j = 0; j < K; j++) {
            #pragma unroll
            for (int u = 0; u < 4; u++) acc2[j][u] = 0ull;
        }
        float cnt_l = 0.f;

        // ---- main pass: two interleaved rows per step ----
        int row = bid * NW1 + warp;
        while (row + TOT_W < N) {
            int rA = row, rB = row + TOT_W;
            const float4* xA = (const float4*)x + (size_t)rA * (D / 4);
            const float4* xB = (const float4*)x + (size_t)rB * (D / 4);
            float4 a0A = __ldg(xA + lane);
            float4 a0B = __ldg(xB + lane);
            float4 a1A = __ldg(xA + lane + 32);
            float4 a1B = __ldg(xB + lane + 32);
            float  xsA = __ldg(g_xsq + rA);
            float  xsB = __ldg(g_xsq + rB);
            u64 pA0 = pk2(a0A.x, a0A.y), pA1 = pk2(a0A.z, a0A.w);
            u64 pA2 = pk2(a1A.x, a1A.y), pA3 = pk2(a1A.z, a1A.w);
            u64 pB0 = pk2(a0B.x, a0B.y), pB1 = pk2(a0B.z, a0B.w);
            u64 pB2 = pk2(a1B.x, a1B.y), pB3 = pk2(a1B.z, a1B.w);
            float dpA[K], dpB[K];
            #pragma unroll
            for (int j = 0; j < K; j++) {
                u64 tA = mul2(pA0, c_pk[j][0]);
                u64 tB = mul2(pB0, c_pk[j][0]);
                tA = fma2(pA1, c_pk[j][1], tA);
                tB = fma2(pB1, c_pk[j][1], tB);
                tA = fma2(pA2, c_pk[j][2], tA);
                tB = fma2(pB2, c_pk[j][2], tB);
                tA = fma2(pA3, c_pk[j][3], tA);
                tB = fma2(pB3, c_pk[j][3], tB);
                float loA, hiA, loB, hiB;
                upk2(tA, loA, hiA); upk2(tB, loB, hiB);
                dpA[j] = loA + hiA; dpB[j] = loB + hiB;
            }
            #pragma unroll
            for (int m = 16; m; m >>= 1) {
                #pragma unroll
                for (int j = 0; j < K; j++) {
                    dpA[j] += __shfl_xor_sync(0xffffffffu, dpA[j], m);
                    dpB[j] += __shfl_xor_sync(0xffffffffu, dpB[j], m);
                }
            }
            float myA = dpA[0], myB = dpB[0];
            #pragma unroll
            for (int j = 1; j < K; j++) {
                myA = (lane == j) ? dpA[j] : myA;
                myB = (lane == j) ? dpB[j] : myB;
            }
            float dA = sqrtf(fmaxf(xsA + csq_l - 2.f * myA, 1e-12f));
            float dB = sqrtf(fmaxf(xsB + csq_l - 2.f * myB, 1e-12f));
            float mnA = wmin8((lane < K) ? dA : 3.4e38f);
            float mnB = wmin8((lane < K) ? dB : 3.4e38f);
            float eA = w_l * __expf(mnA - dA);
            float eB = w_l * __expf(mnB - dB);
            float sA = wsum8(eA);
            float sB = wsum8(eB);
            float rvA = __fdividef(eA, sA);
            float rvB = __fdividef(eB, sB);
            if (lane < K) {
                out_r[(size_t)rA * K + lane] = rvA;
                out_r[(size_t)rB * K + lane] = rvB;
            }
            cnt_l += rvA + rvB;
            #pragma unroll
            for (int j = 0; j < K; j++) {
                float rbA = __shfl_sync(0xffffffffu, rvA, j);
                float rbB = __shfl_sync(0xffffffffu, rvB, j);
                u64 r2A = pk2(rbA, rbA);
                u64 r2B = pk2(rbB, rbB);
                acc2[j][0] = fma2(r2A, pA0, acc2[j][0]);
                acc2[j][1] = fma2(r2A, pA1, acc2[j][1]);
                acc2[j][2] = fma2(r2A, pA2, acc2[j][2]);
                acc2[j][3] = fma2(r2A, pA3, acc2[j][3]);
                acc2[j][0] = fma2(r2B, pB0, acc2[j][0]);
                acc2[j][1] = fma2(r2B, pB1, acc2[j][1]);
                acc2[j][2] = fma2(r2B, pB2, acc2[j][2]);
                acc2[j][3] = fma2(r2B, pB3, acc2[j][3]);
            }
            row += 2 * TOT_W;
        }
        if (row < N) {  // single-row tail
            const float4* xr = (const float4*)x + (size_t)row * (D / 4);
            float4 a0 = __ldg(xr + lane);
            float4 a1 = __ldg(xr + lane + 32);
            float  xs = __ldg(g_xsq + row);
            u64 p0 = pk2(a0.x, a0.y), p1 = pk2(a0.z, a0.w);
            u64 p2 = pk2(a1.x, a1.y), p3 = pk2(a1.z, a1.w);
            float dp[K];
            #pragma unroll
            for (int j = 0; j < K; j++) {
                u64 tt = mul2(p0, c_pk[j][0]);
                tt = fma2(p1, c_pk[j][1], tt);
                tt = fma2(p2, c_pk[j][2], tt);
                tt = fma2(p3, c_pk[j][3], tt);
                float lo, hi; upk2(tt, lo, hi);
                dp[j] = lo + hi;
            }
            #pragma unroll
            for (int j = 0; j < K; j++) dp[j] = wsum(dp[j]);
            float mydp = dp[0];
            #pragma unroll
            for (int j = 1; j < K; j++) mydp = (lane == j) ? dp[j] : mydp;
            float dval = sqrtf(fmaxf(xs + csq_l - 2.f * mydp, 1e-12f));
            float dmn  = wmin8((lane < K) ? dval : 3.4e38f);
            float ev   = w_l * __expf(dmn - dval);
            float ssum = wsum8(ev);
            float rv   = __fdividef(ev, ssum);
            if (lane < K) out_r[(size_t)row * K + lane] = rv;
            cnt_l += rv;
            #pragma unroll
            for (int j = 0; j < K; j++) {
                float rb = __shfl_sync(0xffffffffu, rv, j);
                u64 r2 = pk2(rb, rb);
                acc2[j][0] = fma2(r2, p0, acc2[j][0]);
                acc2[j][1] = fma2(r2, p1, acc2[j][1]);
                acc2[j][2] = fma2(r2, p2, acc2[j][2]);
                acc2[j][3] = fma2(r2, p3, acc2[j][3]);
            }
        }

        // ---- deterministic sequential warp combine ----
        for (int w = 0; w < NW1; w++) {
            if (warp == w) {
                #pragma unroll
                for (int j = 0; j < K; j++) {
                    float lo0, hi0, lo1, hi1;
                    float4 v = s_acc4[j * 64 + lane];
                    upk2(acc2[j][0], lo0, hi0);
                    upk2(acc2[j][1], lo1, hi1);
                    v.x += lo0; v.y += hi0; v.z += lo1; v.w += hi1;
                    s_acc4[j * 64 + lane] = v;
                    v = s_acc4[j * 64 + 32 + lane];
                    upk2(acc2[j][2], lo0, hi0);
                    upk2(acc2[j][3], lo1, hi1);
                    v.x += lo0; v.y += hi0; v.z += lo1; v.w += hi1;
                    s_acc4[j * 64 + 32 + lane] = v;
                }
                if (lane < K) s_cnt[lane] += cnt_l;
            }
            __syncthreads();
        }
        {
            float4* Pb = (float4*)(g_P + (size_t)bid * (KMAX * D));
            for (int i = tid; i < K * 64; i += T1) Pb[i] = s_acc4[i];
            if (tid < K) g_Pc[bid * KMAX + tid] = s_cnt[tid];
        }

        grid_sync();

        // ---- center update: block j < K owns cluster j ----
        if (bid < K) {
            int j = bid;
            double c = (tid < GRID1) ? (double)__ldcg(&g_Pc[tid * KMAX + j]) : 0.0;
            s_red[tid] = c;
            __syncthreads();
            for (int s = 256; s; s >>= 1) {
                if (tid < s && tid + s < T1) s_red[tid] += s_red[tid + s];
                __syncthreads();
            }
            double cnt = s_red[0];
            __syncthreads();

            double v0 = 0.0, v1 = 0.0;
            if (tid < 256) {
                int e = j * D + tid;
                double su[8];
                #pragma unroll
                for (int u = 0; u < 8; u++) su[u] = 0.0;
                int p = 0;
                for (; p + 8 <= GRID1; p += 8) {
                    #pragma unroll
                    for (int u = 0; u < 8; u++)
                        su[u] += (double)__ldcg(&g_P[(size_t)(p + u) * (KMAX * D) + e]);
                }
                for (int u = 0; p < GRID1; p++, u++)
                    su[u] += (double)__ldcg(&g_P[(size_t)p * (KMAX * D) + e]);
                double sum = ((su[0] + su[1]) + (su[2] + su[3]))
                           + ((su[4] + su[5]) + (su[6] + su[7]));
                float ncf = (float)(sum / cnt);
                g_centers[e] = ncf;
                float pv = g_prev[e];
                g_prev[e] = ncf;
                double df = (double)(ncf - pv);
                v0 = df * df;
                v1 = (double)ncf * (double)ncf;
            }
            s_red[tid] = v0;
            __syncthreads();
            for (int s = 256; s; s >>= 1) {
                if (tid < s && tid + s < T1) s_red[tid] += s_red[tid + s];
                __syncthreads();
            }
            if (tid == 0) g_shiftp[j] = s_red[0];
            __syncthreads();
            s_red[tid] = v1;
            __syncthreads();
            for (int s = 256; s; s >>= 1) {
                if (tid < s && tid + s < T1) s_red[tid] += s_red[tid + s];
                __syncthreads();
            }
            if (tid == 0) g_csq[j] = (float)s_red[0];
        }

        grid_sync();

        double sh = 0.0;
        #pragma unroll
        for (int j = 0; j < K; j++) sh += __ldcg(&g_shiftp[j]);
        if (sqrt(sh) < TOLV) break;
    }

    if (bid == 0)
        for (int i = tid; i < K * D; i += T1) out_c[i] = __ldcg(&g_centers[i]);
}

// ---------------------------------------------------------------------------
extern "C" void kernel_launch(void* const* d_in, const int* in_sizes, int n_in,
                              void* d_out, int out_size) {
    const float* x      = (const float*)d_in[0];
    const float* logits = (const float*)d_in[1];
    const float* gumbel = (const float*)d_in[2];
    const float* uinit  = (const float*)d_in[3];
    const int*   maxit  = (const int*)d_in[4];

    int N = in_sizes[0] / D;
    int k = out_size / (N + D);
    if (k < 1) k = 1;
    if (k > KMAX) k = KMAX;

    float* out_c = (float*)d_out;
    float* out_r = out_c + (size_t)k * D;

    k_init<<<1, 256>>>(x, logits, gumbel, uinit, maxit, N);
    k_xsq<<<DB, TM>>>(x, N);
    for (int i = 1; i < k; i++) {
        k_dmin<<<DB, TM>>>(x, N, i);
        k_select<<<1, 1024>>>(x, uinit, N, i);
    }
    switch (k) {
        case 1: k_iter<1><<<GRID1, T1>>>(x, out_r, out_c, N); break;
        case 2: k_iter<2><<<GRID1, T1>>>(x, out_r, out_c, N); break;
        case 3: k_iter<3><<<GRID1, T1>>>(x, out_r, out_c, N); break;
        case 4: k_iter<4><<<GRID1, T1>>>(x, out_r, out_c, N); break;
        case 5: k_iter<5><<<GRID1, T1>>>(x, out_r, out_c, N); break;
        default: k_iter<6><<<GRID1, T1>>>(x, out_r, out_c, N); break;
    }
}